// round 4
// baseline (speedup 1.0000x reference)
#include <cuda_runtime.h>

#define HH 1024
#define WW 1024
#define NPTS 128
#define WPR 32            // 32-bit words per row (1024/32)
#define SENTINEL_D 2048   // > max real 1D distance (1023)

// Bitmap stored COLUMN-MAJOR over word-columns: g_bits[wc*HH + r]
// so the per-point row sweep in search is coalesced (consecutive r).
__device__ unsigned int g_bits[WPR * HH];
__device__ int g_on[NPTS];
__device__ int g_off[NPTS];
__device__ int g_count = 0;   // last-block ticket; reset by last block each run

// ---------------------------------------------------------------------------
// Kernel 1: bitpack. One warp per row; lane loads 8 independent float4s
// (LDG.128, vector regs force true MLP=8). Words assembled with a nibble +
// 3-step shfl_xor OR-tree within 8-lane groups.
// ---------------------------------------------------------------------------
__global__ void bitpack_kernel(const float* __restrict__ hd) {
    int w    = (blockIdx.x * blockDim.x + threadIdx.x) >> 5;   // warp = row
    int lane = threadIdx.x & 31;
    int r    = w;
    const float4* row = reinterpret_cast<const float4*>(hd + r * WW);

    float4 v0 = row[0 * 32 + lane];
    float4 v1 = row[1 * 32 + lane];
    float4 v2 = row[2 * 32 + lane];
    float4 v3 = row[3 * 32 + lane];
    float4 v4 = row[4 * 32 + lane];
    float4 v5 = row[5 * 32 + lane];
    float4 v6 = row[6 * 32 + lane];
    float4 v7 = row[7 * 32 + lane];

    float4 vv[8] = {v0, v1, v2, v3, v4, v5, v6, v7};
    int sh = (lane & 7) * 4;
    #pragma unroll
    for (int j = 0; j < 8; j++) {
        unsigned int nib = (vv[j].x != 0.0f ? 1u : 0u)
                         | (vv[j].y != 0.0f ? 2u : 0u)
                         | (vv[j].z != 0.0f ? 4u : 0u)
                         | (vv[j].w != 0.0f ? 8u : 0u);
        unsigned int wb = nib << sh;
        wb |= __shfl_xor_sync(0xFFFFFFFFu, wb, 1);
        wb |= __shfl_xor_sync(0xFFFFFFFFu, wb, 2);
        wb |= __shfl_xor_sync(0xFFFFFFFFu, wb, 4);
        if ((lane & 7) == 0) {
            int wc = j * 4 + (lane >> 3);      // word-column 0..31
            g_bits[wc * HH + r] = wb;
        }
    }
}

// Nearest set-bit distance from query column q (= wc0*32+bit0) to any set bit
// in word m at word index w. Returns sentinel if m == 0.
__device__ __forceinline__ int nearest_in_word(unsigned int m, int w, int wc0, int bit0) {
    if (m == 0u) return SENTINEL_D;
    if (w == wc0) {
        unsigned int maskLE = (bit0 == 31) ? 0xFFFFFFFFu : ((2u << bit0) - 1u);
        unsigned int lo = m & maskLE;
        unsigned int hi = m & ~maskLE;
        int d = SENTINEL_D;
        if (lo) d = bit0 - (31 - __clz(lo));
        if (hi) { int d2 = (__ffs(hi) - 1) - bit0; d = min(d, d2); }
        return d;
    } else if (w > wc0) {
        return (w << 5) + (__ffs(m) - 1) - ((wc0 << 5) + bit0);
    } else {
        return ((wc0 << 5) + bit0) - ((w << 5) + (31 - __clz(m)));
    }
}

// ---------------------------------------------------------------------------
// Kernel 2: fused per-point search + last-block finalize.
// Block n = point n, thread = one row. Rings 0/+-1 preloaded as independent
// coalesced L2 loads; extension beyond ring 1 is rare at 30%/70% densities.
// Last block to finish computes per-point losses + mean and resets ticket.
// ---------------------------------------------------------------------------
__global__ void search_finalize_kernel(const float* __restrict__ hd,
                                       const int* __restrict__ pred,
                                       float* __restrict__ out) {
    int n  = blockIdx.x;
    int pr = pred[2 * n];       // compared against rows
    int pc = pred[2 * n + 1];   // compared against cols
    int r  = threadIdx.x;       // 1024 threads = 1024 rows

    int wc0  = pc >> 5;
    int bit0 = pc & 31;
    int q32  = (wc0 << 5) + bit0;

    unsigned int m0 = g_bits[wc0 * HH + r];
    bool hasL = (wc0 - 1 >= 0);
    bool hasR = (wc0 + 1 < WPR);
    unsigned int mL = hasL ? g_bits[(wc0 - 1) * HH + r] : 0u;
    unsigned int mR = hasR ? g_bits[(wc0 + 1) * HH + r] : 0u;

    int don  = nearest_in_word(m0,  wc0, wc0, bit0);
    int doff = nearest_in_word(~m0, wc0, wc0, bit0);
    if (hasL) {
        don  = min(don,  nearest_in_word(mL,  wc0 - 1, wc0, bit0));
        doff = min(doff, nearest_in_word(~mL, wc0 - 1, wc0, bit0));
    }
    if (hasR) {
        don  = min(don,  nearest_in_word(mR,  wc0 + 1, wc0, bit0));
        doff = min(doff, nearest_in_word(~mR, wc0 + 1, wc0, bit0));
    }

    {   // extend beyond ring 1 only if the lower bound says it could help
        int cminR = (wc0 + 2 < WPR) ? ((wc0 + 2) << 5) - q32        : SENTINEL_D;
        int cminL = (wc0 - 2 >= 0)  ? q32 - (((wc0 - 2) << 5) + 31) : SENTINEL_D;
        int nextmin = min(cminR, cminL);
        if (don > nextmin || doff > nextmin) {
            #pragma unroll 1
            for (int k = 2; k < WPR + 1; k++) {
                int wr = wc0 + k;
                int wl = wc0 - k;
                if (wr < WPR) {
                    unsigned int m = g_bits[wr * HH + r];
                    don  = min(don,  nearest_in_word(m,  wr, wc0, bit0));
                    doff = min(doff, nearest_in_word(~m, wr, wc0, bit0));
                }
                if (wl >= 0) {
                    unsigned int m = g_bits[wl * HH + r];
                    don  = min(don,  nearest_in_word(m,  wl, wc0, bit0));
                    doff = min(doff, nearest_in_word(~m, wl, wc0, bit0));
                }
                int cR = (wr + 1 < WPR) ? ((wr + 1) << 5) - q32        : SENTINEL_D;
                int cL = (wl - 1 >= 0)  ? q32 - (((wl - 1) << 5) + 31) : SENTINEL_D;
                int nm = min(cR, cL);
                if (don <= nm && doff <= nm) break;
            }
        }
    }
    don  = min(don,  SENTINEL_D);
    doff = min(doff, SENTINEL_D);

    int dr  = r - pr;
    int dr2 = dr * dr;
    int best_on  = dr2 + don * don;
    int best_off = dr2 + doff * doff;

    best_on  = __reduce_min_sync(0xFFFFFFFFu, best_on);
    best_off = __reduce_min_sync(0xFFFFFFFFu, best_off);

    __shared__ int s_on[32];
    __shared__ int s_off[32];
    __shared__ int s_last;
    int wid  = threadIdx.x >> 5;
    int lane = threadIdx.x & 31;
    if (lane == 0) { s_on[wid] = best_on; s_off[wid] = best_off; }
    __syncthreads();
    if (wid == 0) {
        int a = __reduce_min_sync(0xFFFFFFFFu, s_on[lane]);
        int b = __reduce_min_sync(0xFFFFFFFFu, s_off[lane]);
        if (lane == 0) {
            g_on[n]  = a;
            g_off[n] = b;
            __threadfence();
            int ticket = atomicAdd(&g_count, 1);
            s_last = (ticket == NPTS - 1) ? 1 : 0;
        }
    }
    __syncthreads();
    if (!s_last) return;

    // ---- last block: per-point loss + mean (threads 0..127) ----
    __threadfence();
    __shared__ float s_sum[128];
    if (threadIdx.x < NPTS) {
        int i  = threadIdx.x;
        int px = pred[2 * i];
        int py = pred[2 * i + 1];
        bool outside_frame = (px < 0) || (px > HH) || (py < 0) || (py > WW);
        float loss = 0.0f;
        if (!outside_frame) {
            // reference's swapped-index neighbor lookup, JAX-style clamping
            int r0 = min(max(py - 1, 0), HH - 1);
            int r1 = min(max(py,     0), HH - 1);
            int c0 = min(max(px - 1, 0), WW - 1);
            int c1 = min(max(px,     0), WW - 1);
            bool road = (hd[r0 * WW + c0] == 1.0f) || (hd[r0 * WW + c1] == 1.0f) ||
                        (hd[r1 * WW + c0] == 1.0f) || (hd[r1 * WW + c1] == 1.0f);
            float d2on  = (float)g_on[i];
            float d2off = (float)g_off[i];
            const float K1 = 21.7f;
            const float LN2_OVER_K2 = 0.69314718055994531f / 40.0f;
            loss = road ? expf(sqrtf(d2off) * LN2_OVER_K2)
                        : expf(-d2on / K1);
        }
        s_sum[i] = loss;
    }
    __syncthreads();
    if (threadIdx.x < 64) {
        #pragma unroll
        for (int st = 64; st > 0; st >>= 1) {
            if (threadIdx.x < st && st < 128) s_sum[threadIdx.x] += s_sum[threadIdx.x + st];
            __syncwarp(0xFFFFFFFFu);
            if (st == 64) { /* first fold done above */ }
            __syncthreads();
        }
    } else {
        #pragma unroll
        for (int st = 64; st > 0; st >>= 1) __syncthreads();
    }
    if (threadIdx.x == 0) {
        float total = s_sum[0];
        out[0] = total * (1.0f / (float)NPTS);
        g_count = 0;   // reset ticket for next graph replay
    }
}

extern "C" void kernel_launch(void* const* d_in, const int* in_sizes, int n_in,
                              void* d_out, int out_size) {
    const float* hd  = (const float*)d_in[0];
    const int* pred  = (const int*)d_in[1];
    float* out       = (float*)d_out;

    // 1024 warps (one per row): 256 blocks x 128 threads
    bitpack_kernel<<<256, 128>>>(hd);
    // one block per point; last block finalizes
    search_finalize_kernel<<<NPTS, 1024>>>(hd, pred, out);
}

// round 5
// speedup vs baseline: 1.0545x; 1.0545x over previous
#include <cuda_runtime.h>

#define HH 1024
#define WW 1024
#define NPTS 128
#define WPR 32            // 32-bit words per row (1024/32)
#define SENTINEL_D 2048   // > max real 1D distance (1023)

// Bitmap stored COLUMN-MAJOR over word-columns: g_bits[wc*HH + r]
// so the per-point row sweep in search is coalesced (consecutive r).
__device__ unsigned int g_bits[WPR * HH];
__device__ int g_on[NPTS];
__device__ int g_off[NPTS];
__device__ int g_count = 0;   // last-block ticket; reset by last block each run

// ---------------------------------------------------------------------------
// Kernel 1: bitpack. One warp per row; lane loads 8 independent float4s
// (LDG.128, vector regs force true MLP=8). Words assembled with a nibble +
// 3-step shfl_xor OR-tree within 8-lane groups.
// ---------------------------------------------------------------------------
__global__ void bitpack_kernel(const float* __restrict__ hd) {
    int w    = (blockIdx.x * blockDim.x + threadIdx.x) >> 5;   // warp = row
    int lane = threadIdx.x & 31;
    int r    = w;
    const float4* row = reinterpret_cast<const float4*>(hd + r * WW);

    float4 v0 = row[0 * 32 + lane];
    float4 v1 = row[1 * 32 + lane];
    float4 v2 = row[2 * 32 + lane];
    float4 v3 = row[3 * 32 + lane];
    float4 v4 = row[4 * 32 + lane];
    float4 v5 = row[5 * 32 + lane];
    float4 v6 = row[6 * 32 + lane];
    float4 v7 = row[7 * 32 + lane];

    float4 vv[8] = {v0, v1, v2, v3, v4, v5, v6, v7};
    int sh = (lane & 7) * 4;
    #pragma unroll
    for (int j = 0; j < 8; j++) {
        unsigned int nib = (vv[j].x != 0.0f ? 1u : 0u)
                         | (vv[j].y != 0.0f ? 2u : 0u)
                         | (vv[j].z != 0.0f ? 4u : 0u)
                         | (vv[j].w != 0.0f ? 8u : 0u);
        unsigned int wb = nib << sh;
        wb |= __shfl_xor_sync(0xFFFFFFFFu, wb, 1);
        wb |= __shfl_xor_sync(0xFFFFFFFFu, wb, 2);
        wb |= __shfl_xor_sync(0xFFFFFFFFu, wb, 4);
        if ((lane & 7) == 0) {
            int wc = j * 4 + (lane >> 3);      // word-column 0..31
            g_bits[wc * HH + r] = wb;
        }
    }
}

// Nearest set-bit distance from query column q (= wc0*32+bit0) to any set bit
// in word m at word index w. Returns sentinel if m == 0.
__device__ __forceinline__ int nearest_in_word(unsigned int m, int w, int wc0, int bit0) {
    if (m == 0u) return SENTINEL_D;
    if (w == wc0) {
        unsigned int maskLE = (bit0 == 31) ? 0xFFFFFFFFu : ((2u << bit0) - 1u);
        unsigned int lo = m & maskLE;
        unsigned int hi = m & ~maskLE;
        int d = SENTINEL_D;
        if (lo) d = bit0 - (31 - __clz(lo));
        if (hi) { int d2 = (__ffs(hi) - 1) - bit0; d = min(d, d2); }
        return d;
    } else if (w > wc0) {
        return (w << 5) + (__ffs(m) - 1) - ((wc0 << 5) + bit0);
    } else {
        return ((wc0 << 5) + bit0) - ((w << 5) + (31 - __clz(m)));
    }
}

// ---------------------------------------------------------------------------
// Kernel 2: fused per-point search + last-block finalize.
// Block n = point n, thread = one row. Rings 0/+-1 preloaded as independent
// coalesced L2 loads; extension beyond ring 1 is rare at 30%/70% densities.
// Last block to finish computes per-point losses + mean and resets ticket.
// ---------------------------------------------------------------------------
__global__ void search_finalize_kernel(const float* __restrict__ hd,
                                       const int* __restrict__ pred,
                                       float* __restrict__ out) {
    int n  = blockIdx.x;
    int pr = pred[2 * n];       // compared against rows
    int pc = pred[2 * n + 1];   // compared against cols
    int r  = threadIdx.x;       // 1024 threads = 1024 rows

    int wc0  = pc >> 5;
    int bit0 = pc & 31;
    int q32  = (wc0 << 5) + bit0;

    unsigned int m0 = g_bits[wc0 * HH + r];
    bool hasL = (wc0 - 1 >= 0);
    bool hasR = (wc0 + 1 < WPR);
    unsigned int mL = hasL ? g_bits[(wc0 - 1) * HH + r] : 0u;
    unsigned int mR = hasR ? g_bits[(wc0 + 1) * HH + r] : 0u;

    int don  = nearest_in_word(m0,  wc0, wc0, bit0);
    int doff = nearest_in_word(~m0, wc0, wc0, bit0);
    if (hasL) {
        don  = min(don,  nearest_in_word(mL,  wc0 - 1, wc0, bit0));
        doff = min(doff, nearest_in_word(~mL, wc0 - 1, wc0, bit0));
    }
    if (hasR) {
        don  = min(don,  nearest_in_word(mR,  wc0 + 1, wc0, bit0));
        doff = min(doff, nearest_in_word(~mR, wc0 + 1, wc0, bit0));
    }

    {   // extend beyond ring 1 only if the lower bound says it could help
        int cminR = (wc0 + 2 < WPR) ? ((wc0 + 2) << 5) - q32        : SENTINEL_D;
        int cminL = (wc0 - 2 >= 0)  ? q32 - (((wc0 - 2) << 5) + 31) : SENTINEL_D;
        int nextmin = min(cminR, cminL);
        if (don > nextmin || doff > nextmin) {
            #pragma unroll 1
            for (int k = 2; k < WPR + 1; k++) {
                int wr = wc0 + k;
                int wl = wc0 - k;
                if (wr < WPR) {
                    unsigned int m = g_bits[wr * HH + r];
                    don  = min(don,  nearest_in_word(m,  wr, wc0, bit0));
                    doff = min(doff, nearest_in_word(~m, wr, wc0, bit0));
                }
                if (wl >= 0) {
                    unsigned int m = g_bits[wl * HH + r];
                    don  = min(don,  nearest_in_word(m,  wl, wc0, bit0));
                    doff = min(doff, nearest_in_word(~m, wl, wc0, bit0));
                }
                int cR = (wr + 1 < WPR) ? ((wr + 1) << 5) - q32        : SENTINEL_D;
                int cL = (wl - 1 >= 0)  ? q32 - (((wl - 1) << 5) + 31) : SENTINEL_D;
                int nm = min(cR, cL);
                if (don <= nm && doff <= nm) break;
            }
        }
    }
    don  = min(don,  SENTINEL_D);
    doff = min(doff, SENTINEL_D);

    int dr  = r - pr;
    int dr2 = dr * dr;
    int best_on  = dr2 + don * don;
    int best_off = dr2 + doff * doff;

    best_on  = __reduce_min_sync(0xFFFFFFFFu, best_on);
    best_off = __reduce_min_sync(0xFFFFFFFFu, best_off);

    __shared__ int s_on[32];
    __shared__ int s_off[32];
    __shared__ int s_last;
    int wid  = threadIdx.x >> 5;
    int lane = threadIdx.x & 31;
    if (lane == 0) { s_on[wid] = best_on; s_off[wid] = best_off; }
    __syncthreads();
    if (wid == 0) {
        int a = __reduce_min_sync(0xFFFFFFFFu, s_on[lane]);
        int b = __reduce_min_sync(0xFFFFFFFFu, s_off[lane]);
        if (lane == 0) {
            g_on[n]  = a;
            g_off[n] = b;
            __threadfence();
            int ticket = atomicAdd(&g_count, 1);
            s_last = (ticket == NPTS - 1) ? 1 : 0;
        }
    }
    __syncthreads();
    if (!s_last) return;

    // ---- last block: per-point loss + mean (threads 0..127) ----
    __threadfence();
    __shared__ float s_sum[128];
    if (threadIdx.x < NPTS) {
        int i  = threadIdx.x;
        int px = pred[2 * i];
        int py = pred[2 * i + 1];
        bool outside_frame = (px < 0) || (px > HH) || (py < 0) || (py > WW);
        float loss = 0.0f;
        if (!outside_frame) {
            // reference's swapped-index neighbor lookup, JAX-style clamping
            int r0 = min(max(py - 1, 0), HH - 1);
            int r1 = min(max(py,     0), HH - 1);
            int c0 = min(max(px - 1, 0), WW - 1);
            int c1 = min(max(px,     0), WW - 1);
            bool road = (hd[r0 * WW + c0] == 1.0f) || (hd[r0 * WW + c1] == 1.0f) ||
                        (hd[r1 * WW + c0] == 1.0f) || (hd[r1 * WW + c1] == 1.0f);
            float d2on  = (float)g_on[i];
            float d2off = (float)g_off[i];
            const float K1 = 21.7f;
            const float LN2_OVER_K2 = 0.69314718055994531f / 40.0f;
            loss = road ? expf(sqrtf(d2off) * LN2_OVER_K2)
                        : expf(-d2on / K1);
        }
        s_sum[i] = loss;
    }
    __syncthreads();
    if (threadIdx.x < 64) {
        #pragma unroll
        for (int st = 64; st > 0; st >>= 1) {
            if (threadIdx.x < st && st < 128) s_sum[threadIdx.x] += s_sum[threadIdx.x + st];
            __syncwarp(0xFFFFFFFFu);
            if (st == 64) { /* first fold done above */ }
            __syncthreads();
        }
    } else {
        #pragma unroll
        for (int st = 64; st > 0; st >>= 1) __syncthreads();
    }
    if (threadIdx.x == 0) {
        float total = s_sum[0];
        out[0] = total * (1.0f / (float)NPTS);
        g_count = 0;   // reset ticket for next graph replay
    }
}

extern "C" void kernel_launch(void* const* d_in, const int* in_sizes, int n_in,
                              void* d_out, int out_size) {
    const float* hd  = (const float*)d_in[0];
    const int* pred  = (const int*)d_in[1];
    float* out       = (float*)d_out;

    // 1024 warps (one per row): 256 blocks x 128 threads
    bitpack_kernel<<<256, 128>>>(hd);
    // one block per point; last block finalizes
    search_finalize_kernel<<<NPTS, 1024>>>(hd, pred, out);
}

// round 6
// speedup vs baseline: 1.2119x; 1.1493x over previous
#include <cuda_runtime.h>

#define HH 1024
#define WW 1024
#define NPTS 128
#define WPR 32            // 32-bit words per row (1024/32)
#define SENTINEL_D 2048   // > max real 1D distance (1023)

// Bitmap stored COLUMN-MAJOR over word-columns: g_bits[wc*HH + r]
// so the per-point row sweep is coalesced (consecutive r).
__device__ unsigned int g_bits[WPR * HH];
__device__ float g_sum  = 0.0f;
__device__ int   g_bar1 = 0;   // bitpack-done barrier
__device__ int   g_bar2 = 0;   // search-done ticket
// All three reset by the last block each run -> deterministic across replays.

// Nearest set-bit distance from query column q (= wc0*32+bit0) to any set bit
// in word m at word index w. Returns sentinel if m == 0.
__device__ __forceinline__ int nearest_in_word(unsigned int m, int w, int wc0, int bit0) {
    if (m == 0u) return SENTINEL_D;
    if (w == wc0) {
        unsigned int maskLE = (bit0 == 31) ? 0xFFFFFFFFu : ((2u << bit0) - 1u);
        unsigned int lo = m & maskLE;
        unsigned int hi = m & ~maskLE;
        int d = SENTINEL_D;
        if (lo) d = bit0 - (31 - __clz(lo));
        if (hi) { int d2 = (__ffs(hi) - 1) - bit0; d = min(d, d2); }
        return d;
    } else if (w > wc0) {
        return (w << 5) + (__ffs(m) - 1) - ((wc0 << 5) + bit0);
    } else {
        return ((wc0 << 5) + bit0) - ((w << 5) + (31 - __clz(m)));
    }
}

// One kernel does everything: bitpack -> grid barrier -> search -> loss -> mean.
// 128 blocks x 1024 threads; all blocks are resident in wave 1 (128 <= 148 SMs),
// so the spin barrier cannot deadlock.
__global__ void __launch_bounds__(1024, 1)
roadloss_kernel(const float* __restrict__ hd,
                const int*   __restrict__ pred,
                float*       __restrict__ out) {
    int n   = blockIdx.x;     // point index
    int tid = threadIdx.x;

    // Point coords (broadcast loads, issued early).
    int pr = pred[2 * n];       // component 0: compared against rows
    int pc = pred[2 * n + 1];   // component 1: compared against cols

    // Prefetch the 4 neighbor map values for the loss (tid 0 only), so their
    // latency hides under bitpack + barrier. Reference indexes
    // hd_map[py-1..py, px-1..px] with px=pred[:,0], py=pred[:,1] (roles
    // swapped vs the distance computation), JAX-clamped.
    float nv0 = 0.f, nv1 = 0.f, nv2 = 0.f, nv3 = 0.f;
    bool outside_frame = false;
    if (tid == 0) {
        int px = pr, py = pc;
        outside_frame = (px < 0) || (px > HH) || (py < 0) || (py > WW);
        int r0 = min(max(py - 1, 0), HH - 1);
        int r1 = min(max(py,     0), HH - 1);
        int c0 = min(max(px - 1, 0), WW - 1);
        int c1 = min(max(px,     0), WW - 1);
        nv0 = hd[r0 * WW + c0];
        nv1 = hd[r0 * WW + c1];
        nv2 = hd[r1 * WW + c0];
        nv3 = hd[r1 * WW + c1];
    }

    // ---- Phase 1: bitpack. Block n packs rows [8n, 8n+8). ----
    // Thread layout: row_local = tid>>7 (8 rows), c = tid&127 covers cols
    // [8c, 8c+8) via two float4 loads. Byte assembled per thread, OR-combined
    // across 4 lanes with shfl_xor; lane with (c&3)==0 stores the word.
    {
        int rl = tid >> 7;
        int c  = tid & 127;
        int r  = (n << 3) + rl;
        const float4* p = reinterpret_cast<const float4*>(hd + r * WW + (c << 3));
        float4 a = p[0];
        float4 b = p[1];
        unsigned int byte =
              (a.x != 0.0f ?   1u : 0u) | (a.y != 0.0f ?   2u : 0u)
            | (a.z != 0.0f ?   4u : 0u) | (a.w != 0.0f ?   8u : 0u)
            | (b.x != 0.0f ?  16u : 0u) | (b.y != 0.0f ?  32u : 0u)
            | (b.z != 0.0f ?  64u : 0u) | (b.w != 0.0f ? 128u : 0u);
        unsigned int v = byte << ((c & 3) * 8);
        v |= __shfl_xor_sync(0xFFFFFFFFu, v, 1);
        v |= __shfl_xor_sync(0xFFFFFFFFu, v, 2);
        if ((c & 3) == 0) g_bits[(c >> 2) * HH + r] = v;
    }
    __threadfence();          // make this thread's bit stores GPU-visible
    __syncthreads();          // all block stores fenced before arrival

    // ---- Grid barrier: only tid 0 arrives + spins; block held at bar. ----
    if (tid == 0) {
        atomicAdd(&g_bar1, 1);
        while (*(volatile int*)&g_bar1 < NPTS) { }
        __threadfence();      // acquire: order subsequent bit loads
    }
    __syncthreads();

    // ---- Phase 2: separable search. Thread = one row. ----
    int r    = tid;
    int wc0  = pc >> 5;
    int bit0 = pc & 31;
    int q32  = (wc0 << 5) + bit0;

    unsigned int m0 = g_bits[wc0 * HH + r];
    bool hasL = (wc0 - 1 >= 0);
    bool hasR = (wc0 + 1 < WPR);
    unsigned int mL = hasL ? g_bits[(wc0 - 1) * HH + r] : 0u;
    unsigned int mR = hasR ? g_bits[(wc0 + 1) * HH + r] : 0u;

    int don  = nearest_in_word(m0,  wc0, wc0, bit0);
    int doff = nearest_in_word(~m0, wc0, wc0, bit0);
    if (hasL) {
        don  = min(don,  nearest_in_word(mL,  wc0 - 1, wc0, bit0));
        doff = min(doff, nearest_in_word(~mL, wc0 - 1, wc0, bit0));
    }
    if (hasR) {
        don  = min(don,  nearest_in_word(mR,  wc0 + 1, wc0, bit0));
        doff = min(doff, nearest_in_word(~mR, wc0 + 1, wc0, bit0));
    }

    {   // extend beyond ring 1 only if the lower bound says it could help
        int cminR = (wc0 + 2 < WPR) ? ((wc0 + 2) << 5) - q32        : SENTINEL_D;
        int cminL = (wc0 - 2 >= 0)  ? q32 - (((wc0 - 2) << 5) + 31) : SENTINEL_D;
        int nextmin = min(cminR, cminL);
        if (don > nextmin || doff > nextmin) {
            #pragma unroll 1
            for (int k = 2; k < WPR + 1; k++) {
                int wr = wc0 + k;
                int wl = wc0 - k;
                if (wr < WPR) {
                    unsigned int m = g_bits[wr * HH + r];
                    don  = min(don,  nearest_in_word(m,  wr, wc0, bit0));
                    doff = min(doff, nearest_in_word(~m, wr, wc0, bit0));
                }
                if (wl >= 0) {
                    unsigned int m = g_bits[wl * HH + r];
                    don  = min(don,  nearest_in_word(m,  wl, wc0, bit0));
                    doff = min(doff, nearest_in_word(~m, wl, wc0, bit0));
                }
                int cR = (wr + 1 < WPR) ? ((wr + 1) << 5) - q32        : SENTINEL_D;
                int cL = (wl - 1 >= 0)  ? q32 - (((wl - 1) << 5) + 31) : SENTINEL_D;
                int nm = min(cR, cL);
                if (don <= nm && doff <= nm) break;
            }
        }
    }
    don  = min(don,  SENTINEL_D);
    doff = min(doff, SENTINEL_D);

    int dr  = r - pr;
    int dr2 = dr * dr;
    int best_on  = dr2 + don * don;       // ints < 2^21, exact
    int best_off = dr2 + doff * doff;

    best_on  = __reduce_min_sync(0xFFFFFFFFu, best_on);
    best_off = __reduce_min_sync(0xFFFFFFFFu, best_off);

    __shared__ int s_on[32];
    __shared__ int s_off[32];
    int wid  = tid >> 5;
    int lane = tid & 31;
    if (lane == 0) { s_on[wid] = best_on; s_off[wid] = best_off; }
    __syncthreads();

    // ---- Phase 3: tid 0 computes the per-point loss locally and reduces. ----
    if (wid == 0) {
        int a = __reduce_min_sync(0xFFFFFFFFu, s_on[lane]);
        int b = __reduce_min_sync(0xFFFFFFFFu, s_off[lane]);
        if (lane == 0) {
            float loss = 0.0f;
            if (!outside_frame) {
                bool road = (nv0 == 1.0f) || (nv1 == 1.0f) ||
                            (nv2 == 1.0f) || (nv3 == 1.0f);
                const float K1 = 21.7f;
                const float LN2_OVER_K2 = 0.69314718055994531f / 40.0f;
                loss = road ? expf(sqrtf((float)b) * LN2_OVER_K2)
                            : expf(-(float)a / K1);
            }
            atomicAdd(&g_sum, loss);
            __threadfence();                       // release g_sum before ticket
            int ticket = atomicAdd(&g_bar2, 1);
            if (ticket == NPTS - 1) {
                __threadfence();                   // acquire all g_sum adds
                float total = *(volatile float*)&g_sum;
                out[0] = total * (1.0f / (float)NPTS);
                // reset state for the next graph replay
                g_sum  = 0.0f;
                g_bar1 = 0;
                g_bar2 = 0;
                __threadfence();
            }
        }
    }
}

extern "C" void kernel_launch(void* const* d_in, const int* in_sizes, int n_in,
                              void* d_out, int out_size) {
    const float* hd  = (const float*)d_in[0];
    const int* pred  = (const int*)d_in[1];
    float* out       = (float*)d_out;
    roadloss_kernel<<<NPTS, 1024>>>(hd, pred, out);
}